// round 1
// baseline (speedup 1.0000x reference)
#include <cuda_runtime.h>
#include <math.h>

// ---------------------------------------------------------------------------
// PoseConvLSTM: 2 ConvLSTM layers (hc=32, hc=64), 3x3 SAME conv, T=128 steps
// on 64x64 grids, then FC [T, 64*64*64] @ [6, ...]^T.
// Outputs packed: pose[128,6], h1[32,64,64], c1, h2[64,64,64], c2 (787200 f32)
// ---------------------------------------------------------------------------

#define HH 64
#define WW 64
#define NPIX 4096
#define TT 128

// ----- scratch (device globals; no allocation allowed) -----
__device__ float g_ys1[TT * 32 * NPIX];      // 67 MB: layer-1 hidden per step
__device__ float g_ys2[TT * 64 * NPIX];      // 134 MB: layer-2 hidden per step
__device__ float g_c1[32 * NPIX];
__device__ float g_c2[64 * NPIX];
__device__ float g_zerobuf[64 * NPIX];       // zero h0 for t=0 (both layers)
__device__ float g_w1p[32 * 35 * 4 * 12];    // packed weights layer 1
__device__ float g_w2p[64 * 96 * 4 * 12];    // packed weights layer 2

__device__ __forceinline__ float sigmf(float x) {
    return 1.0f / (1.0f + __expf(-x));
}
// tanh via exp: accurate enough (err ~1e-6), no NaN at extremes
__device__ __forceinline__ float tanh_f(float x) {
    return 1.0f - 2.0f / (__expf(2.0f * x) + 1.0f);
}

// ----- zero init -----
__global__ void zero_kernel(float* __restrict__ p, int n) {
    int i = blockIdx.x * blockDim.x + threadIdx.x;
    if (i < n) p[i] = 0.0f;
}

// ----- weight repack: w[(g*hc+co)][cin][3][3] -> wp[((co*CIN+cin)*4+g)*12+k]
// (9 taps padded to 12 floats so each gate's taps are 3 aligned float4 loads)
__global__ void prep_w(const float* __restrict__ w, float* __restrict__ wp,
                       int hc, int cin_tot) {
    int i = blockIdx.x * blockDim.x + threadIdx.x;
    int total = hc * cin_tot * 4 * 12;
    if (i >= total) return;
    int k = i % 12;
    int rest = i / 12;
    int g = rest % 4;
    rest /= 4;
    int cin = rest % cin_tot;
    int co = rest / cin_tot;
    float v = 0.0f;
    if (k < 9) v = w[((g * hc + co) * cin_tot + cin) * 9 + k];
    wp[i] = v;
}

// ----- fused ConvLSTM step -----
// block: 128 threads = 32 quad-pixels (16x8 tile, 4 px/thread in x) x 4 co
// grid:  (32 tiles, HC/4 co-groups)
// smem:  input tile [CIN][10][19] (stride-19 pad vs 4-way bank conflicts)
template <int HC, int CIN, int CX>
__global__ void __launch_bounds__(128) lstm_step(
    const float* __restrict__ xin,    // [CX, 64, 64]   (x part of concat)
    const float* __restrict__ hprev,  // [HC, 64, 64]   (h part of concat)
    const float* __restrict__ wp,     // packed weights
    const float* __restrict__ bias,   // [4*HC]
    float* __restrict__ cst,          // [HC, 64, 64] in/out
    float* __restrict__ hout)         // [HC, 64, 64] out (ys[t])
{
    extern __shared__ float sbuf[];
    const int tid = threadIdx.x;
    const int tile = blockIdx.x;          // 4 x-tiles * 8 y-tiles
    const int cog = blockIdx.y;
    const int tx0 = (tile & 3) << 4;      // 16-wide
    const int ty0 = (tile >> 2) << 3;     // 8-tall
    const int SROW = 19;
    const int SPLANE = 10 * 19;

    // cooperative halo load (10 rows x 18 cols per cin), zero-padded
    for (int idx = tid; idx < CIN * 180; idx += 128) {
        int cin = idx / 180;
        int r = idx - cin * 180;
        int ly = r / 18;
        int lx = r - ly * 18;
        int gy = ty0 + ly - 1;
        int gx = tx0 + lx - 1;
        float v = 0.0f;
        if ((unsigned)gy < 64u && (unsigned)gx < 64u) {
            const float* src = (cin < CX) ? (xin + cin * NPIX)
                                          : (hprev + (cin - CX) * NPIX);
            v = src[gy * 64 + gx];
        }
        sbuf[cin * SPLANE + ly * SROW + lx] = v;
    }
    __syncthreads();

    const int co_l = tid >> 5;            // warp-uniform output channel
    const int pq = tid & 31;
    const int px0 = (pq & 3) << 2;        // 4 pixels along x
    const int py = pq >> 2;               // 0..7
    const int co = (cog << 2) + co_l;

    float acc[4][4];
#pragma unroll
    for (int g = 0; g < 4; ++g) {
        float bv = bias[g * HC + co];
#pragma unroll
        for (int j = 0; j < 4; ++j) acc[g][j] = bv;
    }

    const float4* __restrict__ wq =
        reinterpret_cast<const float4*>(wp) + (size_t)co * CIN * 12;
    const float* sbase = sbuf + py * SROW + px0;

    for (int cin = 0; cin < CIN; ++cin) {
        float win[3][6];
        const float* sr = sbase + cin * SPLANE;
#pragma unroll
        for (int ky = 0; ky < 3; ++ky)
#pragma unroll
            for (int m = 0; m < 6; ++m) win[ky][m] = sr[ky * SROW + m];

        const float4* wc = wq + cin * 12;
#pragma unroll
        for (int g = 0; g < 4; ++g) {
            float4 wa = wc[g * 3 + 0];
            float4 wb = wc[g * 3 + 1];
            float4 wd = wc[g * 3 + 2];
            float w9[9] = {wa.x, wa.y, wa.z, wa.w, wb.x, wb.y, wb.z, wb.w, wd.x};
#pragma unroll
            for (int ky = 0; ky < 3; ++ky)
#pragma unroll
                for (int kx = 0; kx < 3; ++kx) {
                    float wv = w9[ky * 3 + kx];
#pragma unroll
                    for (int j = 0; j < 4; ++j)
                        acc[g][j] = fmaf(win[ky][kx + j], wv, acc[g][j]);
                }
        }
    }

    const int gy = ty0 + py;
#pragma unroll
    for (int j = 0; j < 4; ++j) {
        int idx = co * NPIX + gy * 64 + tx0 + px0 + j;
        float ig = sigmf(acc[0][j]);
        float fg = sigmf(acc[1][j]);
        float og = sigmf(acc[2][j]);
        float gg = tanh_f(acc[3][j]);
        float cn = fmaf(fg, cst[idx], ig * gg);
        cst[idx] = cn;
        hout[idx] = og * tanh_f(cn);
    }
}

// ----- FC: pose[t,j] = ys2[t,:] . fc_w[j,:] + fc_b[j] -----
__global__ void fc_kernel(const float* __restrict__ ys2,
                          const float* __restrict__ fw,
                          const float* __restrict__ fb,
                          float* __restrict__ out) {
    __shared__ float red[6][256];
    const int t = blockIdx.x;
    const int tid = threadIdx.x;
    const float* y = ys2 + (size_t)t * (64 * NPIX);
    float acc[6] = {0.f, 0.f, 0.f, 0.f, 0.f, 0.f};
    const int NK = 64 * NPIX;  // 262144
    for (int k = tid; k < NK; k += 256) {
        float v = y[k];
#pragma unroll
        for (int j = 0; j < 6; ++j)
            acc[j] = fmaf(v, fw[(size_t)j * NK + k], acc[j]);
    }
#pragma unroll
    for (int j = 0; j < 6; ++j) red[j][tid] = acc[j];
    __syncthreads();
    for (int s = 128; s > 0; s >>= 1) {
        if (tid < s) {
#pragma unroll
            for (int j = 0; j < 6; ++j) red[j][tid] += red[j][tid + s];
        }
        __syncthreads();
    }
    if (tid < 6) out[t * 6 + tid] = red[tid][0] + fb[tid];
}

// ----- pack final states into output -----
__global__ void finalize_kernel(const float* __restrict__ ys1,
                                const float* __restrict__ c1,
                                const float* __restrict__ ys2,
                                const float* __restrict__ c2,
                                float* __restrict__ out) {
    int i = blockIdx.x * blockDim.x + threadIdx.x;
    const int N1 = 32 * NPIX;    // 131072
    const int N2 = 64 * NPIX;    // 262144
    if (i < N1) {
        out[768 + i] = ys1[(size_t)(TT - 1) * N1 + i];
    } else if (i < 2 * N1) {
        out[768 + i] = c1[i - N1];
    } else if (i < 2 * N1 + N2) {
        out[768 + i] = ys2[(size_t)(TT - 1) * N2 + (i - 2 * N1)];
    } else if (i < 2 * N1 + 2 * N2) {
        out[768 + i] = c2[i - 2 * N1 - N2];
    }
}

extern "C" void kernel_launch(void* const* d_in, const int* in_sizes, int n_in,
                              void* d_out, int out_size) {
    const float* input = (const float*)d_in[0];  // [128,3,64,64]
    const float* w1    = (const float*)d_in[1];  // [128,35,3,3]
    const float* b1    = (const float*)d_in[2];  // [128]
    const float* w2    = (const float*)d_in[3];  // [256,96,3,3]
    const float* b2    = (const float*)d_in[4];  // [256]
    const float* fcw   = (const float*)d_in[5];  // [6, 262144]
    const float* fcb   = (const float*)d_in[6];  // [6]
    float* out = (float*)d_out;

    float *ys1, *ys2, *c1, *c2, *zb, *w1p, *w2p;
    cudaGetSymbolAddress((void**)&ys1, g_ys1);
    cudaGetSymbolAddress((void**)&ys2, g_ys2);
    cudaGetSymbolAddress((void**)&c1, g_c1);
    cudaGetSymbolAddress((void**)&c2, g_c2);
    cudaGetSymbolAddress((void**)&zb, g_zerobuf);
    cudaGetSymbolAddress((void**)&w1p, g_w1p);
    cudaGetSymbolAddress((void**)&w2p, g_w2p);

    const int sm1 = 35 * 190 * 4;   // 26600 B
    const int sm2 = 96 * 190 * 4;   // 72960 B
    cudaFuncSetAttribute((const void*)lstm_step<32, 35, 3>,
                         cudaFuncAttributeMaxDynamicSharedMemorySize, sm1);
    cudaFuncSetAttribute((const void*)lstm_step<64, 96, 32>,
                         cudaFuncAttributeMaxDynamicSharedMemorySize, sm2);

    // init states / zero buffer each launch (deterministic)
    zero_kernel<<<(32 * NPIX + 255) / 256, 256>>>(c1, 32 * NPIX);
    zero_kernel<<<(64 * NPIX + 255) / 256, 256>>>(c2, 64 * NPIX);
    zero_kernel<<<(64 * NPIX + 255) / 256, 256>>>(zb, 64 * NPIX);
    prep_w<<<(32 * 35 * 48 + 255) / 256, 256>>>(w1, w1p, 32, 35);
    prep_w<<<(64 * 96 * 48 + 255) / 256, 256>>>(w2, w2p, 64, 96);

    dim3 blk(128);
    dim3 g1(32, 8);   // layer1: hc=32 -> 8 co-groups
    dim3 g2(32, 16);  // layer2: hc=64 -> 16 co-groups

    // layer 1 scan
    for (int t = 0; t < TT; ++t) {
        const float* x = input + (size_t)t * 3 * NPIX;
        const float* hp = (t == 0) ? zb : (ys1 + (size_t)(t - 1) * 32 * NPIX);
        float* ho = ys1 + (size_t)t * 32 * NPIX;
        lstm_step<32, 35, 3><<<g1, blk, sm1>>>(x, hp, w1p, b1, c1, ho);
    }
    // layer 2 scan
    for (int t = 0; t < TT; ++t) {
        const float* x = ys1 + (size_t)t * 32 * NPIX;
        const float* hp = (t == 0) ? zb : (ys2 + (size_t)(t - 1) * 64 * NPIX);
        float* ho = ys2 + (size_t)t * 64 * NPIX;
        lstm_step<64, 96, 32><<<g2, blk, sm2>>>(x, hp, w2p, b2, c2, ho);
    }

    fc_kernel<<<TT, 256>>>(ys2, fcw, fcb, out);

    const int NFIN = 2 * 32 * NPIX + 2 * 64 * NPIX;  // 786432
    finalize_kernel<<<(NFIN + 255) / 256, 256>>>(ys1, c1, ys2, c2, out);
}

// round 2
// speedup vs baseline: 2.2771x; 2.2771x over previous
#include <cuda_runtime.h>
#include <math.h>

// ---------------------------------------------------------------------------
// PoseConvLSTM: 2 ConvLSTM layers (hc=32, hc=64), 3x3 SAME conv, T=128 steps
// on 64x64 grids, then FC. fp32 throughout, using packed fma.rn.f32x2
// (sm_103a FFMA2) to reach the full fp32 datapath.
// ---------------------------------------------------------------------------

#define NPIX 4096
#define TT 128

typedef unsigned long long ull;

// ----- scratch (device globals; no allocation allowed) -----
__device__ float g_ys1[TT * 32 * NPIX];
__device__ float g_ys2[TT * 64 * NPIX];
__device__ float g_c1[32 * NPIX];
__device__ float g_c2[64 * NPIX];
__device__ float g_zerobuf[64 * NPIX];
// packed weights: [co][cin][tap(9)][gate(4 = i,f,o,g)] -> each tap = 1 float4
__device__ __align__(16) float g_w1p[32 * 35 * 36];
__device__ __align__(16) float g_w2p[64 * 96 * 36];

__device__ __forceinline__ float sigmf(float x) {
    return 1.0f / (1.0f + __expf(-x));
}
__device__ __forceinline__ float tanh_f(float x) {
    return 1.0f - 2.0f / (__expf(2.0f * x) + 1.0f);
}

// ----- f32x2 helpers -----
__device__ __forceinline__ ull pack2(float lo, float hi) {
    ull r;
    asm("mov.b64 %0, {%1, %2};" : "=l"(r) : "f"(lo), "f"(hi));
    return r;
}
__device__ __forceinline__ ull dup2(float v) {
    ull r;
    asm("mov.b64 %0, {%1, %1};" : "=l"(r) : "f"(v));
    return r;
}
__device__ __forceinline__ void unpack2(ull p, float& lo, float& hi) {
    asm("mov.b64 {%0, %1}, %2;" : "=f"(lo), "=f"(hi) : "l"(p));
}
__device__ __forceinline__ ull ffma2(ull a, ull b, ull c) {
    ull d;
    asm("fma.rn.f32x2 %0, %1, %2, %3;" : "=l"(d) : "l"(a), "l"(b), "l"(c));
    return d;
}

// ----- merged setup: zero states + repack both weight tensors (1 launch) ---
// wp layout: wp[(((co*CIN + cin)*9 + tap)*4 + g)] = w[((g*HC+co)*CIN + cin)*9 + tap]
__global__ void setup_kernel(const float* __restrict__ w1,
                             const float* __restrict__ w2,
                             float* __restrict__ w1p, float* __restrict__ w2p,
                             float* __restrict__ c1, float* __restrict__ c2,
                             float* __restrict__ zb) {
    int i = blockIdx.x * blockDim.x + threadIdx.x;
    const int N_C1 = 32 * NPIX;            // 131072
    const int N_C2 = 64 * NPIX;            // 262144
    const int N_W1 = 32 * 35 * 36;         // 40320
    const int N_W2 = 64 * 96 * 36;         // 221184
    if (i < N_C1) { c1[i] = 0.0f; return; }
    i -= N_C1;
    if (i < N_C2) { c2[i] = 0.0f; return; }
    i -= N_C2;
    if (i < N_C2) { zb[i] = 0.0f; return; }
    i -= N_C2;
    if (i < N_W1) {
        int g = i & 3; int r = i >> 2;
        int t = r % 9; r /= 9;
        int cin = r % 35; int co = r / 35;
        w1p[i] = w1[((g * 32 + co) * 35 + cin) * 9 + t];
        return;
    }
    i -= N_W1;
    if (i < N_W2) {
        int g = i & 3; int r = i >> 2;
        int t = r % 9; r /= 9;
        int cin = r % 96; int co = r / 96;
        w2p[i] = w2[((g * 64 + co) * 96 + cin) * 9 + t];
        return;
    }
}

// ----- fused ConvLSTM step -----
// block: 256 threads = 32 quad-pixels (16x8 tile, 4 px/thread) x 8 co
// grid:  (32 tiles, HC/8 co-groups)
// smem:  input tile [CIN][10][19]
template <int HC, int CIN, int CX>
__global__ void __launch_bounds__(256, 2) lstm_step(
    const float* __restrict__ xin,    // [CX, 64, 64]
    const float* __restrict__ hprev,  // [HC, 64, 64]
    const float* __restrict__ wp,     // packed weights
    const float* __restrict__ bias,   // [4*HC]
    float* __restrict__ cst,          // [HC, 64, 64] in/out
    float* __restrict__ hout)         // [HC, 64, 64]
{
    extern __shared__ float sbuf[];
    const int tid = threadIdx.x;
    const int tile = blockIdx.x;
    const int cog = blockIdx.y;
    const int tx0 = (tile & 3) << 4;      // 16 wide
    const int ty0 = (tile >> 2) << 3;     // 8 tall
    const int SROW = 19;
    const int SPLANE = 190;

    // cooperative halo load: per cin a 10x18 window, zero padded
    for (int idx = tid; idx < CIN * 180; idx += 256) {
        int cin = idx / 180;
        int r = idx - cin * 180;
        int ly = r / 18;
        int lx = r - ly * 18;
        int gy = ty0 + ly - 1;
        int gx = tx0 + lx - 1;
        float v = 0.0f;
        if ((unsigned)gy < 64u && (unsigned)gx < 64u) {
            const float* src = (cin < CX) ? (xin + cin * NPIX)
                                          : (hprev + (cin - CX) * NPIX);
            v = src[gy * 64 + gx];
        }
        sbuf[cin * SPLANE + ly * SROW + lx] = v;
    }
    __syncthreads();

    const int co_l = tid >> 5;            // warp-uniform co within group
    const int pq = tid & 31;
    const int px0 = (pq & 3) << 2;        // 4 px along x
    const int py = pq >> 2;               // 0..7
    const int co = (cog << 3) + co_l;

    // accumulators: per pixel j, pair0 = {z_i, z_f}, pair1 = {z_o, z_g}
    ull acc0[4], acc1[4];
    {
        ull b0 = pack2(bias[0 * HC + co], bias[1 * HC + co]);
        ull b1 = pack2(bias[2 * HC + co], bias[3 * HC + co]);
#pragma unroll
        for (int j = 0; j < 4; ++j) { acc0[j] = b0; acc1[j] = b1; }
    }

    const ulonglong2* __restrict__ wq =
        reinterpret_cast<const ulonglong2*>(wp) + (size_t)co * CIN * 9;
    const float* sbase = sbuf + py * SROW + px0;

#pragma unroll 1
    for (int cin = 0; cin < CIN; ++cin) {
        const float* sr = sbase + cin * SPLANE;
        ull in2[3][6];
#pragma unroll
        for (int ky = 0; ky < 3; ++ky)
#pragma unroll
            for (int m = 0; m < 6; ++m)
                in2[ky][m] = dup2(sr[ky * SROW + m]);

        const ulonglong2* wc = wq + cin * 9;
#pragma unroll
        for (int ky = 0; ky < 3; ++ky)
#pragma unroll
            for (int kx = 0; kx < 3; ++kx) {
                ulonglong2 wt = wc[ky * 3 + kx];   // {w_i,w_f},{w_o,w_g}
#pragma unroll
                for (int j = 0; j < 4; ++j) {
                    acc0[j] = ffma2(in2[ky][kx + j], wt.x, acc0[j]);
                    acc1[j] = ffma2(in2[ky][kx + j], wt.y, acc1[j]);
                }
            }
    }

    const int gy = ty0 + py;
    const int base = co * NPIX + gy * 64 + tx0 + px0;
    float4 cold = *reinterpret_cast<const float4*>(cst + base);
    float cin4[4] = {cold.x, cold.y, cold.z, cold.w};
    float4 cnew, hnew;
    float cn[4], hv[4];
#pragma unroll
    for (int j = 0; j < 4; ++j) {
        float zi, zf, zo, zg;
        unpack2(acc0[j], zi, zf);
        unpack2(acc1[j], zo, zg);
        float ig = sigmf(zi);
        float fg = sigmf(zf);
        float og = sigmf(zo);
        float gg = tanh_f(zg);
        float c = fmaf(fg, cin4[j], ig * gg);
        cn[j] = c;
        hv[j] = og * tanh_f(c);
    }
    cnew.x = cn[0]; cnew.y = cn[1]; cnew.z = cn[2]; cnew.w = cn[3];
    hnew.x = hv[0]; hnew.y = hv[1]; hnew.z = hv[2]; hnew.w = hv[3];
    *reinterpret_cast<float4*>(cst + base) = cnew;
    *reinterpret_cast<float4*>(hout + base) = hnew;
}

// ----- FC: pose[t,j] = ys2[t,:] . fc_w[j,:] + fc_b[j] -----
__global__ void fc_kernel(const float* __restrict__ ys2,
                          const float* __restrict__ fw,
                          const float* __restrict__ fb,
                          float* __restrict__ out) {
    __shared__ float red[6][256];
    const int t = blockIdx.x;
    const int tid = threadIdx.x;
    const float* y = ys2 + (size_t)t * (64 * NPIX);
    float acc[6] = {0.f, 0.f, 0.f, 0.f, 0.f, 0.f};
    const int NK = 64 * NPIX;
    for (int k = tid; k < NK; k += 256) {
        float v = y[k];
#pragma unroll
        for (int j = 0; j < 6; ++j)
            acc[j] = fmaf(v, fw[(size_t)j * NK + k], acc[j]);
    }
#pragma unroll
    for (int j = 0; j < 6; ++j) red[j][tid] = acc[j];
    __syncthreads();
    for (int s = 128; s > 0; s >>= 1) {
        if (tid < s) {
#pragma unroll
            for (int j = 0; j < 6; ++j) red[j][tid] += red[j][tid + s];
        }
        __syncthreads();
    }
    if (tid < 6) out[t * 6 + tid] = red[tid][0] + fb[tid];
}

// ----- pack final states into output -----
__global__ void finalize_kernel(const float* __restrict__ ys1,
                                const float* __restrict__ c1,
                                const float* __restrict__ ys2,
                                const float* __restrict__ c2,
                                float* __restrict__ out) {
    int i = blockIdx.x * blockDim.x + threadIdx.x;
    const int N1 = 32 * NPIX;
    const int N2 = 64 * NPIX;
    if (i < N1) {
        out[768 + i] = ys1[(size_t)(TT - 1) * N1 + i];
    } else if (i < 2 * N1) {
        out[768 + i] = c1[i - N1];
    } else if (i < 2 * N1 + N2) {
        out[768 + i] = ys2[(size_t)(TT - 1) * N2 + (i - 2 * N1)];
    } else if (i < 2 * N1 + 2 * N2) {
        out[768 + i] = c2[i - 2 * N1 - N2];
    }
}

extern "C" void kernel_launch(void* const* d_in, const int* in_sizes, int n_in,
                              void* d_out, int out_size) {
    const float* input = (const float*)d_in[0];  // [128,3,64,64]
    const float* w1    = (const float*)d_in[1];  // [128,35,3,3]
    const float* b1    = (const float*)d_in[2];  // [128]
    const float* w2    = (const float*)d_in[3];  // [256,96,3,3]
    const float* b2    = (const float*)d_in[4];  // [256]
    const float* fcw   = (const float*)d_in[5];  // [6, 262144]
    const float* fcb   = (const float*)d_in[6];  // [6]
    float* out = (float*)d_out;

    float *ys1, *ys2, *c1, *c2, *zb, *w1p, *w2p;
    cudaGetSymbolAddress((void**)&ys1, g_ys1);
    cudaGetSymbolAddress((void**)&ys2, g_ys2);
    cudaGetSymbolAddress((void**)&c1, g_c1);
    cudaGetSymbolAddress((void**)&c2, g_c2);
    cudaGetSymbolAddress((void**)&zb, g_zerobuf);
    cudaGetSymbolAddress((void**)&w1p, g_w1p);
    cudaGetSymbolAddress((void**)&w2p, g_w2p);

    const int sm1 = 35 * 190 * 4;   // 26600 B
    const int sm2 = 96 * 190 * 4;   // 72960 B
    cudaFuncSetAttribute((const void*)lstm_step<32, 35, 3>,
                         cudaFuncAttributeMaxDynamicSharedMemorySize, sm1);
    cudaFuncSetAttribute((const void*)lstm_step<64, 96, 32>,
                         cudaFuncAttributeMaxDynamicSharedMemorySize, sm2);

    // single setup launch so the ncu capture window (-s 5) hits step kernels
    const int NSETUP = 32 * NPIX + 3 * 64 * NPIX + 32 * 35 * 36 + 64 * 96 * 36;
    setup_kernel<<<(NSETUP + 255) / 256, 256>>>(w1, w2, w1p, w2p, c1, c2, zb);

    dim3 blk(256);
    dim3 g1(32, 4);   // layer1: hc=32, 8 co/block
    dim3 g2(32, 8);   // layer2: hc=64, 8 co/block

    // interleaved scans: L1(t) then L2(t); deps hold on the single stream
    for (int t = 0; t < TT; ++t) {
        const float* x1 = input + (size_t)t * 3 * NPIX;
        const float* hp1 = (t == 0) ? zb : (ys1 + (size_t)(t - 1) * 32 * NPIX);
        float* ho1 = ys1 + (size_t)t * 32 * NPIX;
        lstm_step<32, 35, 3><<<g1, blk, sm1>>>(x1, hp1, w1p, b1, c1, ho1);

        const float* x2 = ys1 + (size_t)t * 32 * NPIX;
        const float* hp2 = (t == 0) ? zb : (ys2 + (size_t)(t - 1) * 64 * NPIX);
        float* ho2 = ys2 + (size_t)t * 64 * NPIX;
        lstm_step<64, 96, 32><<<g2, blk, sm2>>>(x2, hp2, w2p, b2, c2, ho2);
    }

    fc_kernel<<<TT, 256>>>(ys2, fcw, fcb, out);

    const int NFIN = 2 * 32 * NPIX + 2 * 64 * NPIX;
    finalize_kernel<<<(NFIN + 255) / 256, 256>>>(ys1, c1, ys2, c2, out);
}

// round 3
// speedup vs baseline: 2.5431x; 1.1168x over previous
#include <cuda_runtime.h>
#include <math.h>

// ---------------------------------------------------------------------------
// PoseConvLSTM: 2 ConvLSTM layers (hc=32, hc=64), 3x3 SAME conv, T=128 steps
// on 64x64 grids, then FC. fp32 with packed fma.rn.f32x2 (sm_103a FFMA2).
// R3: regridded for occupancy + vector LDS with conflict-free lane mapping.
// ---------------------------------------------------------------------------

#define NPIX 4096
#define TT 128

typedef unsigned long long ull;

// ----- scratch -----
__device__ float g_ys1[TT * 32 * NPIX];
__device__ float g_ys2[TT * 64 * NPIX];
__device__ float g_c1[32 * NPIX];
__device__ float g_c2[64 * NPIX];
__device__ float g_zerobuf[64 * NPIX];
// packed weights: [co][cin][tap(9)][gate(4 = i,f,o,g)]
__device__ __align__(16) float g_w1p[32 * 35 * 36];
__device__ __align__(16) float g_w2p[64 * 96 * 36];

__device__ __forceinline__ float sigmf(float x) {
    return 1.0f / (1.0f + __expf(-x));
}
__device__ __forceinline__ float tanh_f(float x) {
    return 1.0f - 2.0f / (__expf(2.0f * x) + 1.0f);
}

// ----- f32x2 helpers -----
__device__ __forceinline__ ull pack2(float lo, float hi) {
    ull r;
    asm("mov.b64 %0, {%1, %2};" : "=l"(r) : "f"(lo), "f"(hi));
    return r;
}
__device__ __forceinline__ ull dup2(float v) {
    ull r;
    asm("mov.b64 %0, {%1, %1};" : "=l"(r) : "f"(v));
    return r;
}
__device__ __forceinline__ void unpack2(ull p, float& lo, float& hi) {
    asm("mov.b64 {%0, %1}, %2;" : "=f"(lo), "=f"(hi) : "l"(p));
}
__device__ __forceinline__ ull ffma2(ull a, ull b, ull c) {
    ull d;
    asm("fma.rn.f32x2 %0, %1, %2, %3;" : "=l"(d) : "l"(a), "l"(b), "l"(c));
    return d;
}

// ----- merged setup (1 launch): zero states + repack both weight tensors ---
__global__ void setup_kernel(const float* __restrict__ w1,
                             const float* __restrict__ w2,
                             float* __restrict__ w1p, float* __restrict__ w2p,
                             float* __restrict__ c1, float* __restrict__ c2,
                             float* __restrict__ zb) {
    int i = blockIdx.x * blockDim.x + threadIdx.x;
    const int N_C1 = 32 * NPIX;
    const int N_C2 = 64 * NPIX;
    const int N_W1 = 32 * 35 * 36;
    const int N_W2 = 64 * 96 * 36;
    if (i < N_C1) { c1[i] = 0.0f; return; }
    i -= N_C1;
    if (i < N_C2) { c2[i] = 0.0f; return; }
    i -= N_C2;
    if (i < N_C2) { zb[i] = 0.0f; return; }
    i -= N_C2;
    if (i < N_W1) {
        int g = i & 3; int r = i >> 2;
        int t = r % 9; r /= 9;
        int cin = r % 35; int co = r / 35;
        w1p[i] = w1[((g * 32 + co) * 35 + cin) * 9 + t];
        return;
    }
    i -= N_W1;
    if (i < N_W2) {
        int g = i & 3; int r = i >> 2;
        int t = r % 9; r /= 9;
        int cin = r % 96; int co = r / 96;
        w2p[i] = w2[((g * 64 + co) * 96 + cin) * 9 + t];
        return;
    }
}

// ----- fused ConvLSTM step -----
// block: 256 thr = 8 co * 32 lanes; lane l: py = l&7, pxi = l>>3, PXT px each
// grid:  ((64/TW)*(64/TH), HC/8)
template <int HC, int CIN, int CX, int TW, int TH, int PXT>
__global__ void __launch_bounds__(256, 2) lstm_step(
    const float* __restrict__ xin,    // [CX, 64, 64]
    const float* __restrict__ hprev,  // [HC, 64, 64]
    const float* __restrict__ wp,     // packed weights
    const float* __restrict__ bias,   // [4*HC]
    float* __restrict__ cst,          // [HC, 64, 64] in/out
    float* __restrict__ hout)         // [HC, 64, 64]
{
    constexpr int SROW = (TW + 2 + 3) & ~3;     // 12 (TW8) / 20 (TW16)
    constexpr int SPLANE = (TH + 2) * SROW;
    constexpr int HWIN = (TH + 2) * (TW + 2);
    constexpr int TILES_X = 64 / TW;

    extern __shared__ float sbuf[];
    const int tid = threadIdx.x;
    const int tile = blockIdx.x;
    const int tx0 = (tile % TILES_X) * TW;
    const int ty0 = (tile / TILES_X) * TH;

    // cooperative halo load, zero padded
    for (int idx = tid; idx < CIN * HWIN; idx += 256) {
        int cin = idx / HWIN;
        int r = idx - cin * HWIN;
        int ly = r / (TW + 2);
        int lx = r - ly * (TW + 2);
        int gy = ty0 + ly - 1;
        int gx = tx0 + lx - 1;
        float v = 0.0f;
        if ((unsigned)gy < 64u && (unsigned)gx < 64u) {
            const float* src = (cin < CX) ? (xin + cin * NPIX)
                                          : (hprev + (cin - CX) * NPIX);
            v = src[gy * 64 + gx];
        }
        sbuf[cin * SPLANE + ly * SROW + lx] = v;
    }
    __syncthreads();

    const int co_l = tid >> 5;
    const int l = tid & 31;
    const int py = l & 7;              // conflict-free phase mapping
    const int pxi = l >> 3;            // 0..3
    const int p0 = pxi * PXT;
    const int co = (blockIdx.y << 3) + co_l;

    ull acc0[4], acc1[4];
    {
        ull b0 = pack2(bias[0 * HC + co], bias[1 * HC + co]);
        ull b1 = pack2(bias[2 * HC + co], bias[3 * HC + co]);
#pragma unroll
        for (int j = 0; j < PXT; ++j) { acc0[j] = b0; acc1[j] = b1; }
    }

    const ulonglong2* __restrict__ wq =
        reinterpret_cast<const ulonglong2*>(wp) + (size_t)co * CIN * 9;
    const float* sbase = sbuf + py * SROW + p0;

#pragma unroll 1
    for (int cin = 0; cin < CIN; ++cin) {
        const float* sr = sbase + cin * SPLANE;
        ull in2[3][6];
#pragma unroll
        for (int ky = 0; ky < 3; ++ky) {
            if (PXT == 4) {
                float4 a = *reinterpret_cast<const float4*>(sr + ky * SROW);
                float4 b = *reinterpret_cast<const float4*>(sr + ky * SROW + 4);
                in2[ky][0] = dup2(a.x); in2[ky][1] = dup2(a.y);
                in2[ky][2] = dup2(a.z); in2[ky][3] = dup2(a.w);
                in2[ky][4] = dup2(b.x); in2[ky][5] = dup2(b.y);
            } else {
                float2 a = *reinterpret_cast<const float2*>(sr + ky * SROW);
                float2 b = *reinterpret_cast<const float2*>(sr + ky * SROW + 2);
                in2[ky][0] = dup2(a.x); in2[ky][1] = dup2(a.y);
                in2[ky][2] = dup2(b.x); in2[ky][3] = dup2(b.y);
            }
        }
        const ulonglong2* wc = wq + cin * 9;
#pragma unroll
        for (int ky = 0; ky < 3; ++ky)
#pragma unroll
            for (int kx = 0; kx < 3; ++kx) {
                ulonglong2 wt = wc[ky * 3 + kx];   // {w_i,w_f},{w_o,w_g}
#pragma unroll
                for (int j = 0; j < PXT; ++j) {
                    acc0[j] = ffma2(in2[ky][kx + j], wt.x, acc0[j]);
                    acc1[j] = ffma2(in2[ky][kx + j], wt.y, acc1[j]);
                }
            }
    }

    const int gy = ty0 + py;
    const int base = co * NPIX + gy * 64 + tx0 + p0;
    float cold[4], cn[4], hv[4];
    if (PXT == 4) {
        float4 cv = *reinterpret_cast<const float4*>(cst + base);
        cold[0] = cv.x; cold[1] = cv.y; cold[2] = cv.z; cold[3] = cv.w;
    } else {
        float2 cv = *reinterpret_cast<const float2*>(cst + base);
        cold[0] = cv.x; cold[1] = cv.y;
    }
#pragma unroll
    for (int j = 0; j < PXT; ++j) {
        float zi, zf, zo, zg;
        unpack2(acc0[j], zi, zf);
        unpack2(acc1[j], zo, zg);
        float ig = sigmf(zi);
        float fg = sigmf(zf);
        float og = sigmf(zo);
        float gg = tanh_f(zg);
        float c = fmaf(fg, cold[j], ig * gg);
        cn[j] = c;
        hv[j] = og * tanh_f(c);
    }
    if (PXT == 4) {
        *reinterpret_cast<float4*>(cst + base) =
            make_float4(cn[0], cn[1], cn[2], cn[3]);
        *reinterpret_cast<float4*>(hout + base) =
            make_float4(hv[0], hv[1], hv[2], hv[3]);
    } else {
        *reinterpret_cast<float2*>(cst + base) = make_float2(cn[0], cn[1]);
        *reinterpret_cast<float2*>(hout + base) = make_float2(hv[0], hv[1]);
    }
}

// ----- FC -----
__global__ void fc_kernel(const float* __restrict__ ys2,
                          const float* __restrict__ fw,
                          const float* __restrict__ fb,
                          float* __restrict__ out) {
    __shared__ float red[6][256];
    const int t = blockIdx.x;
    const int tid = threadIdx.x;
    const float* y = ys2 + (size_t)t * (64 * NPIX);
    float acc[6] = {0.f, 0.f, 0.f, 0.f, 0.f, 0.f};
    const int NK = 64 * NPIX;
    for (int k = tid; k < NK; k += 256) {
        float v = y[k];
#pragma unroll
        for (int j = 0; j < 6; ++j)
            acc[j] = fmaf(v, fw[(size_t)j * NK + k], acc[j]);
    }
#pragma unroll
    for (int j = 0; j < 6; ++j) red[j][tid] = acc[j];
    __syncthreads();
    for (int s = 128; s > 0; s >>= 1) {
        if (tid < s) {
#pragma unroll
            for (int j = 0; j < 6; ++j) red[j][tid] += red[j][tid + s];
        }
        __syncthreads();
    }
    if (tid < 6) out[t * 6 + tid] = red[tid][0] + fb[tid];
}

// ----- pack final states -----
__global__ void finalize_kernel(const float* __restrict__ ys1,
                                const float* __restrict__ c1,
                                const float* __restrict__ ys2,
                                const float* __restrict__ c2,
                                float* __restrict__ out) {
    int i = blockIdx.x * blockDim.x + threadIdx.x;
    const int N1 = 32 * NPIX;
    const int N2 = 64 * NPIX;
    if (i < N1) {
        out[768 + i] = ys1[(size_t)(TT - 1) * N1 + i];
    } else if (i < 2 * N1) {
        out[768 + i] = c1[i - N1];
    } else if (i < 2 * N1 + N2) {
        out[768 + i] = ys2[(size_t)(TT - 1) * N2 + (i - 2 * N1)];
    } else if (i < 2 * N1 + 2 * N2) {
        out[768 + i] = c2[i - 2 * N1 - N2];
    }
}

extern "C" void kernel_launch(void* const* d_in, const int* in_sizes, int n_in,
                              void* d_out, int out_size) {
    const float* input = (const float*)d_in[0];
    const float* w1    = (const float*)d_in[1];
    const float* b1    = (const float*)d_in[2];
    const float* w2    = (const float*)d_in[3];
    const float* b2    = (const float*)d_in[4];
    const float* fcw   = (const float*)d_in[5];
    const float* fcb   = (const float*)d_in[6];
    float* out = (float*)d_out;

    float *ys1, *ys2, *c1, *c2, *zb, *w1p, *w2p;
    cudaGetSymbolAddress((void**)&ys1, g_ys1);
    cudaGetSymbolAddress((void**)&ys2, g_ys2);
    cudaGetSymbolAddress((void**)&c1, g_c1);
    cudaGetSymbolAddress((void**)&c2, g_c2);
    cudaGetSymbolAddress((void**)&zb, g_zerobuf);
    cudaGetSymbolAddress((void**)&w1p, g_w1p);
    cudaGetSymbolAddress((void**)&w2p, g_w2p);

    // L1: 8x8 tiles, 2 px/thread -> grid (64,4); smem 35*120*4 = 16800
    // L2: 16x8 tiles, 4 px/thread -> grid (32,8); smem 96*200*4 = 76800
    const int sm1 = 35 * 120 * 4;
    const int sm2 = 96 * 200 * 4;
    cudaFuncSetAttribute((const void*)lstm_step<32, 35, 3, 8, 8, 2>,
                         cudaFuncAttributeMaxDynamicSharedMemorySize, sm1);
    cudaFuncSetAttribute((const void*)lstm_step<64, 96, 32, 16, 8, 4>,
                         cudaFuncAttributeMaxDynamicSharedMemorySize, sm2);

    const int NSETUP = 32 * NPIX + 3 * 64 * NPIX + 32 * 35 * 36 + 64 * 96 * 36;
    setup_kernel<<<(NSETUP + 255) / 256, 256>>>(w1, w2, w1p, w2p, c1, c2, zb);

    dim3 blk(256);
    dim3 g1(64, 4);
    dim3 g2(32, 8);

    for (int t = 0; t < TT; ++t) {
        const float* x1 = input + (size_t)t * 3 * NPIX;
        const float* hp1 = (t == 0) ? zb : (ys1 + (size_t)(t - 1) * 32 * NPIX);
        float* ho1 = ys1 + (size_t)t * 32 * NPIX;
        lstm_step<32, 35, 3, 8, 8, 2><<<g1, blk, sm1>>>(x1, hp1, w1p, b1, c1, ho1);

        const float* x2 = ys1 + (size_t)t * 32 * NPIX;
        const float* hp2 = (t == 0) ? zb : (ys2 + (size_t)(t - 1) * 64 * NPIX);
        float* ho2 = ys2 + (size_t)t * 64 * NPIX;
        lstm_step<64, 96, 32, 16, 8, 4><<<g2, blk, sm2>>>(x2, hp2, w2p, b2, c2, ho2);
    }

    fc_kernel<<<TT, 256>>>(ys2, fcw, fcb, out);

    const int NFIN = 2 * 32 * NPIX + 2 * 64 * NPIX;
    finalize_kernel<<<(NFIN + 255) / 256, 256>>>(ys1, c1, ys2, c2, out);
}